// round 1
// baseline (speedup 1.0000x reference)
#include <cuda_runtime.h>
#include <math.h>

// ---------------------------------------------------------------------------
// Problem constants: B=4, S=2048, D=1024, H=4, HD=256
// Inputs: hidden_states, Wq, Wk, Wv, Wo, bo, betas, mem, z
// Output buffer: out[8388608] | mem_new[262144] | z_new[1024]
// ---------------------------------------------------------------------------

#define NROWS 8192          // B*S
#define DIM   1024
#define NHEAD 4
#define HDIM  256
#define OUT_ELEMS   (NROWS * DIM)          // 8388608
#define MEM_ELEMS   (NHEAD * HDIM * HDIM)  // 262144
#define Z_ELEMS     (NHEAD * HDIM)         // 1024

// ---------------- scratch (device globals: allocation-free) ----------------
__device__ float g_Q   [OUT_ELEMS];
__device__ float g_K   [OUT_ELEMS];
__device__ float g_V   [OUT_ELEMS];
__device__ float g_SQ  [OUT_ELEMS];
__device__ float g_SK  [OUT_ELEMS];
__device__ float g_AT  [OUT_ELEMS];   // attention out, then blended out
__device__ float g_AN  [OUT_ELEMS];   // A_mem numerator
__device__ float g_DN  [OUT_ELEMS];   // delta numerator, then (v - delta)
__device__ float g_MT  [MEM_ELEMS];   // mem transposed [h][e][d]
__device__ float g_DQ  [NROWS * NHEAD];
__device__ float g_DK  [NROWS * NHEAD];
__device__ float g_MP  [16 * MEM_ELEMS];  // split-K partials for mem update
__device__ float g_ZP  [32 * DIM];        // partial column sums for z update

// ---------------------------------------------------------------------------
// Generic NT SGEMM: C[M,N] = A[M,K] @ B[N,K]^T  (+ optional bias[col])
// BM=BN=128, BK=8, 256 threads, 8x8 microtiles. grid = (N/128, M/128).
// ---------------------------------------------------------------------------
__global__ __launch_bounds__(256) void sgemm_nt(
    const float* __restrict__ A, int lda,
    const float* __restrict__ B, int ldb,
    float* __restrict__ C, int ldc,
    int K, const float* __restrict__ bias)
{
    __shared__ float As[8][128];
    __shared__ float Bs[8][128];
    const int t  = threadIdx.x;
    const int tx = t & 15, ty = t >> 4;
    const int lr = t >> 1;          // 0..127 : tile row loaded by this thread
    const int lc = (t & 1) << 2;    // 0 or 4 : k-offset (float4)
    const float* Ag = A + (size_t)(blockIdx.y * 128 + lr) * lda + lc;
    const float* Bg = B + (size_t)(blockIdx.x * 128 + lr) * ldb + lc;

    float acc[8][8];
#pragma unroll
    for (int i = 0; i < 8; i++)
#pragma unroll
        for (int j = 0; j < 8; j++) acc[i][j] = 0.f;

    for (int k0 = 0; k0 < K; k0 += 8) {
        float4 a = *(const float4*)(Ag + k0);
        float4 b = *(const float4*)(Bg + k0);
        __syncthreads();
        As[lc + 0][lr] = a.x; As[lc + 1][lr] = a.y;
        As[lc + 2][lr] = a.z; As[lc + 3][lr] = a.w;
        Bs[lc + 0][lr] = b.x; Bs[lc + 1][lr] = b.y;
        Bs[lc + 2][lr] = b.z; Bs[lc + 3][lr] = b.w;
        __syncthreads();
#pragma unroll
        for (int kk = 0; kk < 8; kk++) {
            float av[8], bv[8];
            *(float4*)(av)     = *(const float4*)&As[kk][ty * 8];
            *(float4*)(av + 4) = *(const float4*)&As[kk][ty * 8 + 4];
            *(float4*)(bv)     = *(const float4*)&Bs[kk][tx * 8];
            *(float4*)(bv + 4) = *(const float4*)&Bs[kk][tx * 8 + 4];
#pragma unroll
            for (int i = 0; i < 8; i++)
#pragma unroll
                for (int j = 0; j < 8; j++)
                    acc[i][j] += av[i] * bv[j];
        }
    }

#pragma unroll
    for (int i = 0; i < 8; i++) {
        int row = blockIdx.y * 128 + ty * 8 + i;
#pragma unroll
        for (int j = 0; j < 8; j++) {
            int col = blockIdx.x * 128 + tx * 8 + j;
            float v = acc[i][j];
            if (bias) v += bias[col];
            C[(size_t)row * ldc + col] = v;
        }
    }
}

// ---------------------------------------------------------------------------
// Flash attention (fp32, causal, no 1/sqrt(d) scale), Br=Bc=64, 256 threads.
// smem: Qs/Ks/Vs [64][257] (pad 257 -> low-conflict scalar LDS), Ps [64][65].
// Thread (tx,ty): score micro 4x4 (rows ty*4.., cols tx*4..);
// O accumulator rows ty*4.. , cols {tx + 16*i}.
// ---------------------------------------------------------------------------
#define FA_PAD 257
#define FA_SMEM_FLOATS (3 * 64 * FA_PAD + 64 * 65)
#define FA_SMEM_BYTES  (FA_SMEM_FLOATS * 4)

__global__ __launch_bounds__(256) void flash_kernel(
    const float* __restrict__ Q, const float* __restrict__ K,
    const float* __restrict__ V, float* __restrict__ O)
{
    extern __shared__ float sm[];
    float* Qs = sm;
    float* Ks = sm + 64 * FA_PAD;
    float* Vs = sm + 2 * 64 * FA_PAD;
    float* Ps = sm + 3 * 64 * FA_PAD;   // [64][65]

    const int t  = threadIdx.x;
    const int tx = t & 15, ty = t >> 4;
    const int qt = gridDim.x - 1 - blockIdx.x;   // reversed for load balance
    const int bh = blockIdx.y;
    const int b  = bh >> 2, h = bh & 3;
    const int q0 = qt * 64;
    const int r0 = ty * 4;
    const int c0 = tx * 4;

    const float* Qg = Q + ((size_t)(b * 2048 + q0)) * 1024 + h * 256;
#pragma unroll
    for (int i = 0; i < 16; i++) {
        int f = i * 256 + t;
        int r = f >> 6;
        int c = (f & 63) << 2;
        float4 v = *(const float4*)(Qg + (size_t)r * 1024 + c);
        float* d = Qs + r * FA_PAD + c;
        d[0] = v.x; d[1] = v.y; d[2] = v.z; d[3] = v.w;
    }

    float m[4], l[4], Oa[4][16];
#pragma unroll
    for (int q = 0; q < 4; q++) {
        m[q] = -INFINITY; l[q] = 0.f;
#pragma unroll
        for (int i = 0; i < 16; i++) Oa[q][i] = 0.f;
    }

    for (int kt = 0; kt <= qt; kt++) {
        const int k0 = kt * 64;
        const float* Kg = K + ((size_t)(b * 2048 + k0)) * 1024 + h * 256;
        const float* Vg = V + ((size_t)(b * 2048 + k0)) * 1024 + h * 256;
        __syncthreads();   // prev PV done: Ks/Vs/Ps free
#pragma unroll
        for (int i = 0; i < 16; i++) {
            int f = i * 256 + t;
            int r = f >> 6;
            int c = (f & 63) << 2;
            float4 kv = *(const float4*)(Kg + (size_t)r * 1024 + c);
            float4 vv = *(const float4*)(Vg + (size_t)r * 1024 + c);
            float* dk = Ks + r * FA_PAD + c;
            dk[0] = kv.x; dk[1] = kv.y; dk[2] = kv.z; dk[3] = kv.w;
            float* dv = Vs + r * FA_PAD + c;
            dv[0] = vv.x; dv[1] = vv.y; dv[2] = vv.z; dv[3] = vv.w;
        }
        __syncthreads();

        float s_[4][4];
#pragma unroll
        for (int q = 0; q < 4; q++)
#pragma unroll
            for (int i = 0; i < 4; i++) s_[q][i] = 0.f;

#pragma unroll 2
        for (int kk = 0; kk < 256; kk++) {
            float qv[4], kv[4];
#pragma unroll
            for (int q = 0; q < 4; q++) qv[q] = Qs[(r0 + q) * FA_PAD + kk];
#pragma unroll
            for (int i = 0; i < 4; i++) kv[i] = Ks[(c0 + i) * FA_PAD + kk];
#pragma unroll
            for (int q = 0; q < 4; q++)
#pragma unroll
                for (int i = 0; i < 4; i++)
                    s_[q][i] += qv[q] * kv[i];
        }

        if (kt == qt) {
#pragma unroll
            for (int q = 0; q < 4; q++)
#pragma unroll
                for (int i = 0; i < 4; i++)
                    if (c0 + i > r0 + q) s_[q][i] = -INFINITY;
        }

#pragma unroll
        for (int q = 0; q < 4; q++) {
            float mt = fmaxf(fmaxf(s_[q][0], s_[q][1]), fmaxf(s_[q][2], s_[q][3]));
#pragma unroll
            for (int off = 8; off >= 1; off >>= 1)
                mt = fmaxf(mt, __shfl_xor_sync(0xffffffffu, mt, off));
            float mn   = fmaxf(m[q], mt);
            float corr = __expf(m[q] - mn);
            float rs = 0.f;
#pragma unroll
            for (int i = 0; i < 4; i++) {
                float p = __expf(s_[q][i] - mn);
                s_[q][i] = p; rs += p;
            }
#pragma unroll
            for (int off = 8; off >= 1; off >>= 1)
                rs += __shfl_xor_sync(0xffffffffu, rs, off);
            l[q] = l[q] * corr + rs;
            m[q] = mn;
#pragma unroll
            for (int i = 0; i < 16; i++) Oa[q][i] *= corr;
#pragma unroll
            for (int i = 0; i < 4; i++) Ps[(r0 + q) * 65 + c0 + i] = s_[q][i];
        }
        __syncthreads();   // Ps fully written

        for (int j = 0; j < 64; j++) {
            float pv[4];
#pragma unroll
            for (int q = 0; q < 4; q++) pv[q] = Ps[(r0 + q) * 65 + j];
#pragma unroll
            for (int i = 0; i < 16; i++) {
                float vv = Vs[j * FA_PAD + tx + 16 * i];
#pragma unroll
                for (int q = 0; q < 4; q++) Oa[q][i] += pv[q] * vv;
            }
        }
    }

#pragma unroll
    for (int q = 0; q < 4; q++) {
        float inv = 1.f / l[q];
        size_t base = ((size_t)(b * 2048 + q0 + r0 + q)) * 1024 + h * 256 + tx;
#pragma unroll
        for (int i = 0; i < 16; i++)
            O[base + 16 * i] = Oa[q][i] * inv;
    }
}

// ---------------------------------------------------------------------------
// Elementwise / small kernels
// ---------------------------------------------------------------------------
__global__ void elu_kernel(const float* __restrict__ X, float* __restrict__ Y, int n)
{
    int i = blockIdx.x * 256 + threadIdx.x;
    if (i < n) {
        float x = X[i];
        Y[i] = x > 0.f ? x + 1.f : __expf(x);   // elu(x)+1
    }
}

__global__ void transpose_mem(const float* __restrict__ mem, float* __restrict__ memT)
{
    int i = blockIdx.x * 256 + threadIdx.x;     // 262144
    int h = i >> 16, rem = i & 65535, e = rem >> 8, d = rem & 255;
    memT[i] = mem[h * 65536 + d * 256 + e];
}

// one warp per (row, head): dot(s_row_h, z_h)
__global__ void dotz_kernel(const float* __restrict__ S, const float* __restrict__ z,
                            float* __restrict__ out)
{
    int gw   = (blockIdx.x * 256 + threadIdx.x) >> 5;
    int lane = threadIdx.x & 31;
    int row = gw >> 2, h = gw & 3;
    const float* a  = S + (size_t)row * 1024 + h * 256;
    const float* zz = z + h * 256;
    float s = 0.f;
#pragma unroll
    for (int k = 0; k < 8; k++) s += a[lane + 32 * k] * zz[lane + 32 * k];
#pragma unroll
    for (int off = 16; off >= 1; off >>= 1) s += __shfl_xor_sync(0xffffffffu, s, off);
    if (lane == 0) out[gw] = s;
}

__global__ void blend_kernel(float* __restrict__ attn, const float* __restrict__ Anum,
                             const float* __restrict__ dq, const float* __restrict__ betas)
{
    int i = blockIdx.x * 256 + threadIdx.x;
    int row = i >> 10, col = i & 1023, h = col >> 8;
    float g  = 1.f / (1.f + __expf(-betas[h]));
    float am = Anum[i] / (dq[row * 4 + h] + 1e-6f);
    attn[i]  = g * am + (1.f - g) * attn[i];
}

__global__ void vmd_kernel(float* __restrict__ dnum, const float* __restrict__ V,
                           const float* __restrict__ dk)
{
    int i = blockIdx.x * 256 + threadIdx.x;
    int row = i >> 10, h = (i >> 8) & 3;
    dnum[i] = V[i] - dnum[i] / (dk[row * 4 + h] + 1e-6f);
}

// ---------------------------------------------------------------------------
// mem update: partials[kc][h][d][e] = sum_{rows in chunk} sk[row,d]*vmd[row,e]
// grid = (16 k-chunks, 16 = dt*4+et, 4 heads), 256 threads, 4x4 micro.
// ---------------------------------------------------------------------------
__global__ __launch_bounds__(256) void memnew_part(
    const float* __restrict__ SK, const float* __restrict__ VMD,
    float* __restrict__ part)
{
    __shared__ float As[16][64];
    __shared__ float Bs[16][64];
    const int kc = blockIdx.x, h = blockIdx.z;
    const int dt = blockIdx.y >> 2, et = blockIdx.y & 3;
    const int t  = threadIdx.x;
    const int tx = t & 15, ty = t >> 4;
    const int lr = t >> 4, lc4 = (t & 15) << 2;

    const float* Ag = SK  + h * 256 + dt * 64 + lc4;
    const float* Bg = VMD + h * 256 + et * 64 + lc4;
    float acc[4][4];
#pragma unroll
    for (int i = 0; i < 4; i++)
#pragma unroll
        for (int j = 0; j < 4; j++) acc[i][j] = 0.f;

    const int rbase = kc * 512;
    for (int k0 = 0; k0 < 512; k0 += 16) {
        size_t row = (size_t)(rbase + k0 + lr) * 1024;
        float4 a = *(const float4*)(Ag + row);
        float4 b = *(const float4*)(Bg + row);
        __syncthreads();
        *(float4*)&As[lr][lc4] = a;
        *(float4*)&Bs[lr][lc4] = b;
        __syncthreads();
#pragma unroll
        for (int kk = 0; kk < 16; kk++) {
            float av[4], bv[4];
#pragma unroll
            for (int i = 0; i < 4; i++) av[i] = As[kk][ty * 4 + i];
#pragma unroll
            for (int j = 0; j < 4; j++) bv[j] = Bs[kk][tx * 4 + j];
#pragma unroll
            for (int i = 0; i < 4; i++)
#pragma unroll
                for (int j = 0; j < 4; j++)
                    acc[i][j] += av[i] * bv[j];
        }
    }

    float* P = part + (size_t)(kc * 4 + h) * 65536
             + (dt * 64 + ty * 4) * 256 + et * 64 + tx * 4;
#pragma unroll
    for (int i = 0; i < 4; i++)
#pragma unroll
        for (int j = 0; j < 4; j++)
            P[i * 256 + j] = acc[i][j];
}

__global__ void memred_kernel(const float* __restrict__ part,
                              const float* __restrict__ mem, float* __restrict__ out)
{
    int i = blockIdx.x * 256 + threadIdx.x;   // 262144
    int h = i >> 16, rem = i & 65535;
    float s = 0.f;
#pragma unroll
    for (int kc = 0; kc < 16; kc++) s += part[(size_t)(kc * 4 + h) * 65536 + rem];
    out[i] = mem[i] + 0.25f * s;
}

__global__ void zpart_kernel(const float* __restrict__ SK, float* __restrict__ zp)
{
    int col = blockIdx.x * 256 + threadIdx.x;
    int r0  = blockIdx.y * 256;
    float s = 0.f;
    for (int r = 0; r < 256; r++) s += SK[(size_t)(r0 + r) * 1024 + col];
    zp[blockIdx.y * 1024 + col] = s;
}

__global__ void zred_kernel(const float* __restrict__ zp, const float* __restrict__ z,
                            float* __restrict__ out)
{
    int col = blockIdx.x * 256 + threadIdx.x;   // 1024
    float s = 0.f;
#pragma unroll
    for (int c = 0; c < 32; c++) s += zp[c * 1024 + col];
    out[col] = z[col] + 0.25f * s;
}

// ---------------------------------------------------------------------------
// Launch
// ---------------------------------------------------------------------------
extern "C" void kernel_launch(void* const* d_in, const int* in_sizes, int n_in,
                              void* d_out, int out_size)
{
    const float* X     = (const float*)d_in[0];
    const float* Wq    = (const float*)d_in[1];
    const float* Wk    = (const float*)d_in[2];
    const float* Wv    = (const float*)d_in[3];
    const float* Wo    = (const float*)d_in[4];
    const float* bo    = (const float*)d_in[5];
    const float* betas = (const float*)d_in[6];
    const float* mem   = (const float*)d_in[7];
    const float* z     = (const float*)d_in[8];

    float* out    = (float*)d_out;
    float* memout = out + OUT_ELEMS;
    float* zout   = out + OUT_ELEMS + MEM_ELEMS;

    float *Q, *K, *V, *SQ, *SK, *AT, *AN, *DN, *MT, *DQ, *DK, *MP, *ZP;
    cudaGetSymbolAddress((void**)&Q,  g_Q);
    cudaGetSymbolAddress((void**)&K,  g_K);
    cudaGetSymbolAddress((void**)&V,  g_V);
    cudaGetSymbolAddress((void**)&SQ, g_SQ);
    cudaGetSymbolAddress((void**)&SK, g_SK);
    cudaGetSymbolAddress((void**)&AT, g_AT);
    cudaGetSymbolAddress((void**)&AN, g_AN);
    cudaGetSymbolAddress((void**)&DN, g_DN);
    cudaGetSymbolAddress((void**)&MT, g_MT);
    cudaGetSymbolAddress((void**)&DQ, g_DQ);
    cudaGetSymbolAddress((void**)&DK, g_DK);
    cudaGetSymbolAddress((void**)&MP, g_MP);
    cudaGetSymbolAddress((void**)&ZP, g_ZP);

    cudaFuncSetAttribute(flash_kernel,
                         cudaFuncAttributeMaxDynamicSharedMemorySize, FA_SMEM_BYTES);

    dim3 g1024(8, 64);   // N=1024 tiles x, M=8192 tiles y
    dim3 g256 (2, 64);   // N=256  tiles x

    // projections
    sgemm_nt<<<g1024, 256>>>(X, 1024, Wq, 1024, Q, 1024, 1024, nullptr);
    sgemm_nt<<<g1024, 256>>>(X, 1024, Wk, 1024, K, 1024, 1024, nullptr);
    sgemm_nt<<<g1024, 256>>>(X, 1024, Wv, 1024, V, 1024, 1024, nullptr);

    // feature maps + mem transpose
    elu_kernel<<<OUT_ELEMS / 256, 256>>>(Q, SQ, OUT_ELEMS);
    elu_kernel<<<OUT_ELEMS / 256, 256>>>(K, SK, OUT_ELEMS);
    transpose_mem<<<MEM_ELEMS / 256, 256>>>(mem, MT);

    // causal attention
    flash_kernel<<<dim3(32, 16), 256, FA_SMEM_BYTES>>>(Q, K, V, AT);

    // linear-attention numerators (per head)
    for (int h = 0; h < 4; h++) {
        sgemm_nt<<<g256, 256>>>(SQ + h * 256, 1024, MT + h * 65536, 256,
                                AN + h * 256, 1024, 256, nullptr);
        sgemm_nt<<<g256, 256>>>(SK + h * 256, 1024, MT + h * 65536, 256,
                                DN + h * 256, 1024, 256, nullptr);
    }

    // denominators
    dotz_kernel<<<4096, 256>>>(SQ, z, DQ);
    dotz_kernel<<<4096, 256>>>(SK, z, DK);

    // blend + (v - delta)
    blend_kernel<<<OUT_ELEMS / 256, 256>>>(AT, AN, DQ, betas);
    vmd_kernel  <<<OUT_ELEMS / 256, 256>>>(DN, V, DK);

    // output projection (+bias) -> d_out
    sgemm_nt<<<g1024, 256>>>(AT, 1024, Wo, 1024, out, 1024, 1024, bo);

    // mem_new
    memnew_part <<<dim3(16, 16, 4), 256>>>(SK, DN, MP);
    memred_kernel<<<MEM_ELEMS / 256, 256>>>(MP, mem, memout);

    // z_new
    zpart_kernel<<<dim3(4, 32), 256>>>(SK, ZP);
    zred_kernel <<<4, 256>>>(ZP, z, zout);
}

// round 3
// speedup vs baseline: 1.3268x; 1.3268x over previous
#include <cuda_runtime.h>
#include <math.h>

// ---------------------------------------------------------------------------
// Problem constants: B=4, S=2048, D=1024, H=4, HD=256
// ---------------------------------------------------------------------------

#define NROWS 8192          // B*S
#define DIM   1024
#define NHEAD 4
#define HDIM  256
#define OUT_ELEMS   (NROWS * DIM)          // 8388608
#define MEM_ELEMS   (NHEAD * HDIM * HDIM)  // 262144
#define Z_ELEMS     (NHEAD * HDIM)         // 1024

// ---------------- scratch (device globals: allocation-free) ----------------
__device__ float g_Q   [OUT_ELEMS];
__device__ float g_K   [OUT_ELEMS];
__device__ float g_V   [OUT_ELEMS];
__device__ float g_SQ  [OUT_ELEMS];
__device__ float g_SK  [OUT_ELEMS];
__device__ float g_AT  [OUT_ELEMS];   // attention out, then blended out
__device__ float g_AN  [OUT_ELEMS];   // A_mem numerator
__device__ float g_DN  [OUT_ELEMS];   // delta numerator, then (v - delta)
__device__ float g_MT  [MEM_ELEMS];   // mem transposed [h][e][d]
__device__ float g_DQ  [NROWS * NHEAD];
__device__ float g_DK  [NROWS * NHEAD];
__device__ float g_MP  [16 * MEM_ELEMS];  // split-K partials for mem update
__device__ float g_ZP  [32 * DIM];        // partial column sums for z update

// ---------------------------------------------------------------------------
// tf32 helpers
// ---------------------------------------------------------------------------
__device__ __forceinline__ unsigned f2tf(float x) {
    unsigned r;
    asm("cvt.rna.tf32.f32 %0, %1;" : "=r"(r) : "f"(x));
    return r;
}

__device__ __forceinline__ void mma_tf32(float* c, const unsigned* a, const unsigned* b) {
    asm volatile(
        "mma.sync.aligned.m16n8k8.row.col.f32.tf32.tf32.f32 "
        "{%0,%1,%2,%3}, {%4,%5,%6,%7}, {%8,%9}, {%0,%1,%2,%3};"
        : "+f"(c[0]), "+f"(c[1]), "+f"(c[2]), "+f"(c[3])
        : "r"(a[0]), "r"(a[1]), "r"(a[2]), "r"(a[3]), "r"(b[0]), "r"(b[1]));
}

// ---------------------------------------------------------------------------
// tf32 tensor-core NT GEMM: C[M,N] = A[M,K] @ B[N,K]^T  (+ optional bias[col])
// Block 128x128x32, 256 threads = 8 warps, warp tile 32x64 (2x8 m16n8k8 atoms).
// SPLIT=true: 3xTF32 error compensation (fp32-grade accuracy).
// Requires M%128==0, N%128==0, K%32==0.
// ---------------------------------------------------------------------------
template<bool SPLIT>
__global__ __launch_bounds__(256) void tf32_gemm_nt(
    const float* __restrict__ A, int lda,
    const float* __restrict__ B, int ldb,
    float* __restrict__ C, int ldc,
    int K, const float* __restrict__ bias)
{
    __shared__ float As[128][36];
    __shared__ float Bs[128][36];

    const int t    = threadIdx.x;
    const int lane = t & 31;
    const int wid  = t >> 5;
    const int wm   = (wid >> 1) * 32;     // warp M offset 0,32,64,96
    const int wn   = (wid & 1) * 64;      // warp N offset 0,64
    const int grp  = lane >> 2;           // 0..7
    const int tg   = lane & 3;            // 0..3

    const int lrow = t >> 3;              // 0..31
    const int lcol = (t & 7) << 2;        // 0,4,...,28
    const float* Ap = A + (size_t)(blockIdx.y * 128 + lrow) * lda + lcol;
    const float* Bp = B + (size_t)(blockIdx.x * 128 + lrow) * ldb + lcol;

    float acc[2][8][4];
#pragma unroll
    for (int ma = 0; ma < 2; ma++)
#pragma unroll
        for (int na = 0; na < 8; na++)
#pragma unroll
            for (int i = 0; i < 4; i++) acc[ma][na][i] = 0.f;

    float4 ra[4], rb[4];

    // fetch chunk 0
#pragma unroll
    for (int i = 0; i < 4; i++) {
        ra[i] = *(const float4*)(Ap + (size_t)(32 * i) * lda);
        rb[i] = *(const float4*)(Bp + (size_t)(32 * i) * ldb);
    }
#pragma unroll
    for (int i = 0; i < 4; i++) {
        *(float4*)&As[lrow + 32 * i][lcol] = ra[i];
        *(float4*)&Bs[lrow + 32 * i][lcol] = rb[i];
    }
    __syncthreads();

    for (int k0 = 0; k0 < K; k0 += 32) {
        const bool more = (k0 + 32) < K;
        if (more) {
#pragma unroll
            for (int i = 0; i < 4; i++) {
                ra[i] = *(const float4*)(Ap + (size_t)(32 * i) * lda + k0 + 32);
                rb[i] = *(const float4*)(Bp + (size_t)(32 * i) * ldb + k0 + 32);
            }
        }

#pragma unroll
        for (int k8 = 0; k8 < 32; k8 += 8) {
            unsigned ah[2][4], al[2][4];
#pragma unroll
            for (int ma = 0; ma < 2; ma++) {
                float v0 = As[wm + ma * 16 + grp    ][k8 + tg];
                float v1 = As[wm + ma * 16 + grp + 8][k8 + tg];
                float v2 = As[wm + ma * 16 + grp    ][k8 + tg + 4];
                float v3 = As[wm + ma * 16 + grp + 8][k8 + tg + 4];
                ah[ma][0] = f2tf(v0); ah[ma][1] = f2tf(v1);
                ah[ma][2] = f2tf(v2); ah[ma][3] = f2tf(v3);
                if (SPLIT) {
                    al[ma][0] = f2tf(v0 - __uint_as_float(ah[ma][0]));
                    al[ma][1] = f2tf(v1 - __uint_as_float(ah[ma][1]));
                    al[ma][2] = f2tf(v2 - __uint_as_float(ah[ma][2]));
                    al[ma][3] = f2tf(v3 - __uint_as_float(ah[ma][3]));
                }
            }
            unsigned bh[8][2], bl[8][2];
#pragma unroll
            for (int na = 0; na < 8; na++) {
                float u0 = Bs[wn + na * 8 + grp][k8 + tg];
                float u1 = Bs[wn + na * 8 + grp][k8 + tg + 4];
                bh[na][0] = f2tf(u0); bh[na][1] = f2tf(u1);
                if (SPLIT) {
                    bl[na][0] = f2tf(u0 - __uint_as_float(bh[na][0]));
                    bl[na][1] = f2tf(u1 - __uint_as_float(bh[na][1]));
                }
            }
#pragma unroll
            for (int ma = 0; ma < 2; ma++)
#pragma unroll
                for (int na = 0; na < 8; na++) {
                    mma_tf32(acc[ma][na], ah[ma], bh[na]);
                    if (SPLIT) {
                        mma_tf32(acc[ma][na], ah[ma], bl[na]);
                        mma_tf32(acc[ma][na], al[ma], bh[na]);
                    }
                }
        }

        __syncthreads();
        if (more) {
#pragma unroll
            for (int i = 0; i < 4; i++) {
                *(float4*)&As[lrow + 32 * i][lcol] = ra[i];
                *(float4*)&Bs[lrow + 32 * i][lcol] = rb[i];
            }
            __syncthreads();
        }
    }

    // epilogue
#pragma unroll
    for (int ma = 0; ma < 2; ma++)
#pragma unroll
        for (int half = 0; half < 2; half++) {
            int row = blockIdx.y * 128 + wm + ma * 16 + grp + half * 8;
#pragma unroll
            for (int na = 0; na < 8; na++) {
                int col = blockIdx.x * 128 + wn + na * 8 + tg * 2;
                float2 v;
                v.x = acc[ma][na][half * 2 + 0];
                v.y = acc[ma][na][half * 2 + 1];
                if (bias) { v.x += bias[col]; v.y += bias[col + 1]; }
                *(float2*)&C[(size_t)row * ldc + col] = v;
            }
        }
}

// ---------------------------------------------------------------------------
// Flash attention (fp32, causal, no 1/sqrt(d) scale), Br=Bc=64, 256 threads.
// ---------------------------------------------------------------------------
#define FA_PAD 257
#define FA_SMEM_FLOATS (3 * 64 * FA_PAD + 64 * 65)
#define FA_SMEM_BYTES  (FA_SMEM_FLOATS * 4)

__global__ __launch_bounds__(256) void flash_kernel(
    const float* __restrict__ Q, const float* __restrict__ K,
    const float* __restrict__ V, float* __restrict__ O)
{
    extern __shared__ float sm[];
    float* Qs = sm;
    float* Ks = sm + 64 * FA_PAD;
    float* Vs = sm + 2 * 64 * FA_PAD;
    float* Ps = sm + 3 * 64 * FA_PAD;   // [64][65]

    const int t  = threadIdx.x;
    const int tx = t & 15, ty = t >> 4;
    const int qt = gridDim.x - 1 - blockIdx.x;
    const int bh = blockIdx.y;
    const int b  = bh >> 2, h = bh & 3;
    const int q0 = qt * 64;
    const int r0 = ty * 4;
    const int c0 = tx * 4;

    const float* Qg = Q + ((size_t)(b * 2048 + q0)) * 1024 + h * 256;
#pragma unroll
    for (int i = 0; i < 16; i++) {
        int f = i * 256 + t;
        int r = f >> 6;
        int c = (f & 63) << 2;
        float4 v = *(const float4*)(Qg + (size_t)r * 1024 + c);
        float* d = Qs + r * FA_PAD + c;
        d[0] = v.x; d[1] = v.y; d[2] = v.z; d[3] = v.w;
    }

    float m[4], l[4], Oa[4][16];
#pragma unroll
    for (int q = 0; q < 4; q++) {
        m[q] = -INFINITY; l[q] = 0.f;
#pragma unroll
        for (int i = 0; i < 16; i++) Oa[q][i] = 0.f;
    }

    for (int kt = 0; kt <= qt; kt++) {
        const int k0 = kt * 64;
        const float* Kg = K + ((size_t)(b * 2048 + k0)) * 1024 + h * 256;
        const float* Vg = V + ((size_t)(b * 2048 + k0)) * 1024 + h * 256;
        __syncthreads();
#pragma unroll
        for (int i = 0; i < 16; i++) {
            int f = i * 256 + t;
            int r = f >> 6;
            int c = (f & 63) << 2;
            float4 kv = *(const float4*)(Kg + (size_t)r * 1024 + c);
            float4 vv = *(const float4*)(Vg + (size_t)r * 1024 + c);
            float* dk = Ks + r * FA_PAD + c;
            dk[0] = kv.x; dk[1] = kv.y; dk[2] = kv.z; dk[3] = kv.w;
            float* dv = Vs + r * FA_PAD + c;
            dv[0] = vv.x; dv[1] = vv.y; dv[2] = vv.z; dv[3] = vv.w;
        }
        __syncthreads();

        float s_[4][4];
#pragma unroll
        for (int q = 0; q < 4; q++)
#pragma unroll
            for (int i = 0; i < 4; i++) s_[q][i] = 0.f;

#pragma unroll 2
        for (int kk = 0; kk < 256; kk++) {
            float qv[4], kv[4];
#pragma unroll
            for (int q = 0; q < 4; q++) qv[q] = Qs[(r0 + q) * FA_PAD + kk];
#pragma unroll
            for (int i = 0; i < 4; i++) kv[i] = Ks[(c0 + i) * FA_PAD + kk];
#pragma unroll
            for (int q = 0; q < 4; q++)
#pragma unroll
                for (int i = 0; i < 4; i++)
                    s_[q][i] += qv[q] * kv[i];
        }

        if (kt == qt) {
#pragma unroll
            for (int q = 0; q < 4; q++)
#pragma unroll
                for (int i = 0; i < 4; i++)
                    if (c0 + i > r0 + q) s_[q][i] = -INFINITY;
        }

#pragma unroll
        for (int q = 0; q < 4; q++) {
            float mt = fmaxf(fmaxf(s_[q][0], s_[q][1]), fmaxf(s_[q][2], s_[q][3]));
#pragma unroll
            for (int off = 8; off >= 1; off >>= 1)
                mt = fmaxf(mt, __shfl_xor_sync(0xffffffffu, mt, off));
            float mn   = fmaxf(m[q], mt);
            float corr = __expf(m[q] - mn);
            float rs = 0.f;
#pragma unroll
            for (int i = 0; i < 4; i++) {
                float p = __expf(s_[q][i] - mn);
                s_[q][i] = p; rs += p;
            }
#pragma unroll
            for (int off = 8; off >= 1; off >>= 1)
                rs += __shfl_xor_sync(0xffffffffu, rs, off);
            l[q] = l[q] * corr + rs;
            m[q] = mn;
#pragma unroll
            for (int i = 0; i < 16; i++) Oa[q][i] *= corr;
#pragma unroll
            for (int i = 0; i < 4; i++) Ps[(r0 + q) * 65 + c0 + i] = s_[q][i];
        }
        __syncthreads();

        for (int j = 0; j < 64; j++) {
            float pv[4];
#pragma unroll
            for (int q = 0; q < 4; q++) pv[q] = Ps[(r0 + q) * 65 + j];
#pragma unroll
            for (int i = 0; i < 16; i++) {
                float vv = Vs[j * FA_PAD + tx + 16 * i];
#pragma unroll
                for (int q = 0; q < 4; q++) Oa[q][i] += pv[q] * vv;
            }
        }
    }

#pragma unroll
    for (int q = 0; q < 4; q++) {
        float inv = 1.f / l[q];
        size_t base = ((size_t)(b * 2048 + q0 + r0 + q)) * 1024 + h * 256 + tx;
#pragma unroll
        for (int i = 0; i < 16; i++)
            O[base + 16 * i] = Oa[q][i] * inv;
    }
}

// ---------------------------------------------------------------------------
// Elementwise / small kernels
// ---------------------------------------------------------------------------
__global__ void elu_kernel(const float* __restrict__ X, float* __restrict__ Y, int n)
{
    int i = blockIdx.x * 256 + threadIdx.x;
    if (i < n) {
        float x = X[i];
        Y[i] = x > 0.f ? x + 1.f : __expf(x);   // elu(x)+1
    }
}

__global__ void transpose_mem(const float* __restrict__ mem, float* __restrict__ memT)
{
    int i = blockIdx.x * 256 + threadIdx.x;     // 262144
    int h = i >> 16, rem = i & 65535, e = rem >> 8, d = rem & 255;
    memT[i] = mem[h * 65536 + d * 256 + e];
}

__global__ void dotz_kernel(const float* __restrict__ S, const float* __restrict__ z,
                            float* __restrict__ out)
{
    int gw   = (blockIdx.x * 256 + threadIdx.x) >> 5;
    int lane = threadIdx.x & 31;
    int row = gw >> 2, h = gw & 3;
    const float* a  = S + (size_t)row * 1024 + h * 256;
    const float* zz = z + h * 256;
    float s = 0.f;
#pragma unroll
    for (int k = 0; k < 8; k++) s += a[lane + 32 * k] * zz[lane + 32 * k];
#pragma unroll
    for (int off = 16; off >= 1; off >>= 1) s += __shfl_xor_sync(0xffffffffu, s, off);
    if (lane == 0) out[gw] = s;
}

__global__ void blend_kernel(float* __restrict__ attn, const float* __restrict__ Anum,
                             const float* __restrict__ dq, const float* __restrict__ betas)
{
    int i = blockIdx.x * 256 + threadIdx.x;
    int row = i >> 10, col = i & 1023, h = col >> 8;
    float g  = 1.f / (1.f + __expf(-betas[h]));
    float am = Anum[i] / (dq[row * 4 + h] + 1e-6f);
    attn[i]  = g * am + (1.f - g) * attn[i];
}

__global__ void vmd_kernel(float* __restrict__ dnum, const float* __restrict__ V,
                           const float* __restrict__ dk)
{
    int i = blockIdx.x * 256 + threadIdx.x;
    int row = i >> 10, h = (i >> 8) & 3;
    dnum[i] = V[i] - dnum[i] / (dk[row * 4 + h] + 1e-6f);
}

// ---------------------------------------------------------------------------
// mem update split-K partials + reduce
// ---------------------------------------------------------------------------
__global__ __launch_bounds__(256) void memnew_part(
    const float* __restrict__ SK, const float* __restrict__ VMD,
    float* __restrict__ part)
{
    __shared__ float As[16][64];
    __shared__ float Bs[16][64];
    const int kc = blockIdx.x, h = blockIdx.z;
    const int dt = blockIdx.y >> 2, et = blockIdx.y & 3;
    const int t  = threadIdx.x;
    const int tx = t & 15, ty = t >> 4;
    const int lr = t >> 4, lc4 = (t & 15) << 2;

    const float* Ag = SK  + h * 256 + dt * 64 + lc4;
    const float* Bg = VMD + h * 256 + et * 64 + lc4;
    float acc[4][4];
#pragma unroll
    for (int i = 0; i < 4; i++)
#pragma unroll
        for (int j = 0; j < 4; j++) acc[i][j] = 0.f;

    const int rbase = kc * 512;
    for (int k0 = 0; k0 < 512; k0 += 16) {
        size_t row = (size_t)(rbase + k0 + lr) * 1024;
        float4 a = *(const float4*)(Ag + row);
        float4 b = *(const float4*)(Bg + row);
        __syncthreads();
        *(float4*)&As[lr][lc4] = a;
        *(float4*)&Bs[lr][lc4] = b;
        __syncthreads();
#pragma unroll
        for (int kk = 0; kk < 16; kk++) {
            float av[4], bv[4];
#pragma unroll
            for (int i = 0; i < 4; i++) av[i] = As[kk][ty * 4 + i];
#pragma unroll
            for (int j = 0; j < 4; j++) bv[j] = Bs[kk][tx * 4 + j];
#pragma unroll
            for (int i = 0; i < 4; i++)
#pragma unroll
                for (int j = 0; j < 4; j++)
                    acc[i][j] += av[i] * bv[j];
        }
    }

    float* P = part + (size_t)(kc * 4 + h) * 65536
             + (dt * 64 + ty * 4) * 256 + et * 64 + tx * 4;
#pragma unroll
    for (int i = 0; i < 4; i++)
#pragma unroll
        for (int j = 0; j < 4; j++)
            P[i * 256 + j] = acc[i][j];
}

__global__ void memred_kernel(const float* __restrict__ part,
                              const float* __restrict__ mem, float* __restrict__ out)
{
    int i = blockIdx.x * 256 + threadIdx.x;   // 262144
    int h = i >> 16, rem = i & 65535;
    float s = 0.f;
#pragma unroll
    for (int kc = 0; kc < 16; kc++) s += part[(size_t)(kc * 4 + h) * 65536 + rem];
    out[i] = mem[i] + 0.25f * s;
}

__global__ void zpart_kernel(const float* __restrict__ SK, float* __restrict__ zp)
{
    int col = blockIdx.x * 256 + threadIdx.x;
    int r0  = blockIdx.y * 256;
    float s = 0.f;
    for (int r = 0; r < 256; r++) s += SK[(size_t)(r0 + r) * 1024 + col];
    zp[blockIdx.y * 1024 + col] = s;
}

__global__ void zred_kernel(const float* __restrict__ zp, const float* __restrict__ z,
                            float* __restrict__ out)
{
    int col = blockIdx.x * 256 + threadIdx.x;   // 1024
    float s = 0.f;
#pragma unroll
    for (int c = 0; c < 32; c++) s += zp[c * 1024 + col];
    out[col] = z[col] + 0.25f * s;
}

// ---------------------------------------------------------------------------
// Launch
// ---------------------------------------------------------------------------
extern "C" void kernel_launch(void* const* d_in, const int* in_sizes, int n_in,
                              void* d_out, int out_size)
{
    const float* X     = (const float*)d_in[0];
    const float* Wq    = (const float*)d_in[1];
    const float* Wk    = (const float*)d_in[2];
    const float* Wv    = (const float*)d_in[3];
    const float* Wo    = (const float*)d_in[4];
    const float* bo    = (const float*)d_in[5];
    const float* betas = (const float*)d_in[6];
    const float* mem   = (const float*)d_in[7];
    const float* z     = (const float*)d_in[8];

    float* out    = (float*)d_out;
    float* memout = out + OUT_ELEMS;
    float* zout   = out + OUT_ELEMS + MEM_ELEMS;

    float *Q, *K, *V, *SQ, *SK, *AT, *AN, *DN, *MT, *DQ, *DK, *MP, *ZP;
    cudaGetSymbolAddress((void**)&Q,  g_Q);
    cudaGetSymbolAddress((void**)&K,  g_K);
    cudaGetSymbolAddress((void**)&V,  g_V);
    cudaGetSymbolAddress((void**)&SQ, g_SQ);
    cudaGetSymbolAddress((void**)&SK, g_SK);
    cudaGetSymbolAddress((void**)&AT, g_AT);
    cudaGetSymbolAddress((void**)&AN, g_AN);
    cudaGetSymbolAddress((void**)&DN, g_DN);
    cudaGetSymbolAddress((void**)&MT, g_MT);
    cudaGetSymbolAddress((void**)&DQ, g_DQ);
    cudaGetSymbolAddress((void**)&DK, g_DK);
    cudaGetSymbolAddress((void**)&MP, g_MP);
    cudaGetSymbolAddress((void**)&ZP, g_ZP);

    cudaFuncSetAttribute(flash_kernel,
                         cudaFuncAttributeMaxDynamicSharedMemorySize, FA_SMEM_BYTES);

    dim3 g1024(8, 64);   // N=1024 tiles x, M=8192 tiles y
    dim3 g256 (2, 64);   // N=256  tiles x

    // projections (3xTF32 split: attention-path fidelity)
    tf32_gemm_nt<true><<<g1024, 256>>>(X, 1024, Wq, 1024, Q, 1024, 1024, nullptr);
    tf32_gemm_nt<true><<<g1024, 256>>>(X, 1024, Wk, 1024, K, 1024, 1024, nullptr);
    tf32_gemm_nt<true><<<g1024, 256>>>(X, 1024, Wv, 1024, V, 1024, 1024, nullptr);

    // feature maps + mem transpose
    elu_kernel<<<OUT_ELEMS / 256, 256>>>(Q, SQ, OUT_ELEMS);
    elu_kernel<<<OUT_ELEMS / 256, 256>>>(K, SK, OUT_ELEMS);
    transpose_mem<<<MEM_ELEMS / 256, 256>>>(mem, MT);

    // causal attention
    flash_kernel<<<dim3(32, 16), 256, FA_SMEM_BYTES>>>(Q, K, V, AT);

    // linear-attention numerators (per head; plain tf32)
    for (int h = 0; h < 4; h++) {
        tf32_gemm_nt<false><<<g256, 256>>>(SQ + h * 256, 1024, MT + h * 65536, 256,
                                           AN + h * 256, 1024, 256, nullptr);
        tf32_gemm_nt<false><<<g256, 256>>>(SK + h * 256, 1024, MT + h * 65536, 256,
                                           DN + h * 256, 1024, 256, nullptr);
    }

    // denominators
    dotz_kernel<<<4096, 256>>>(SQ, z, DQ);
    dotz_kernel<<<4096, 256>>>(SK, z, DK);

    // blend + (v - delta)
    blend_kernel<<<OUT_ELEMS / 256, 256>>>(AT, AN, DQ, betas);
    vmd_kernel  <<<OUT_ELEMS / 256, 256>>>(DN, V, DK);

    // output projection (+bias) -> d_out (plain tf32, rounded operands)
    tf32_gemm_nt<false><<<g1024, 256>>>(AT, 1024, Wo, 1024, out, 1024, 1024, bo);

    // mem_new
    memnew_part <<<dim3(16, 16, 4), 256>>>(SK, DN, MP);
    memred_kernel<<<MEM_ELEMS / 256, 256>>>(MP, mem, memout);

    // z_new
    zpart_kernel<<<dim3(4, 32), 256>>>(SK, ZP);
    zred_kernel <<<4, 256>>>(ZP, z, zout);
}